// round 6
// baseline (speedup 1.0000x reference)
#include <cuda_runtime.h>
#include <cstdint>

#define N_NODES 4096
#define F_IN    256
#define F_OUT   64
#define HDIM    64
#define MAX_DEG 64
#define ALPHA   0.2f

#define NB      16                 // nodes per LSTM block
#define NCHUNK  (N_NODES / NB)     // 256 chunks
#define GP      260                // gates smem pitch (floats), 16B-aligned rows

// ------------------------- device scratch (no mallocs allowed) -------------
__device__ float d_Wh [N_NODES * F_OUT];
__device__ float d_Wh2[N_NODES * F_OUT];
__device__ float d_e1 [N_NODES];
__device__ float d_e2 [N_NODES];
__device__ int   d_ord[N_NODES * MAX_DEG];
__device__ int   d_bins[64];
__device__ int   d_binoff[64];
__device__ int   d_sorted[N_NODES];
__device__ int   d_work;

// ------------------------- K1: Wh = h @ W ----------------------------------
// grid 128, block 256, dyn smem = 96KB (W 64KB + 32 h rows 32KB)
__global__ void k_wh(const float* __restrict__ h, const float* __restrict__ W) {
    extern __shared__ float sm[];
    float* Wsm = sm;                       // [256][64]
    float* hsm = sm + F_IN * F_OUT;        // [32][256]
    const int tid = threadIdx.x;
    const int r0  = blockIdx.x * 32;
    for (int i = tid; i < F_IN * F_OUT; i += 256) Wsm[i] = W[i];
    for (int i = tid; i < 32 * F_IN;    i += 256) hsm[i] = h[(size_t)r0 * F_IN + i];
    __syncthreads();
    const int f  = tid & 63;
    const int rq = tid >> 6;               // 0..3, each handles 8 rows
    float acc[8];
#pragma unroll
    for (int j = 0; j < 8; j++) acc[j] = 0.f;
    for (int k = 0; k < F_IN; k++) {
        const float w = Wsm[k * F_OUT + f];
#pragma unroll
        for (int j = 0; j < 8; j++)
            acc[j] = fmaf(w, hsm[(rq * 8 + j) * F_IN + k], acc[j]);
    }
#pragma unroll
    for (int j = 0; j < 8; j++)
        d_Wh[(r0 + rq * 8 + j) * F_OUT + f] = acc[j];
}

// ------------------------- K1b: e1 = Wh@a1, e2 = Wh@a2 ---------------------
// grid 512, block 256 (one warp per row)
__global__ void k_e(const float* __restrict__ a) {
    const int row  = (blockIdx.x * blockDim.x + threadIdx.x) >> 5;
    const int lane = threadIdx.x & 31;
    if (row >= N_NODES) return;
    const float v0 = d_Wh[row * F_OUT + lane];
    const float v1 = d_Wh[row * F_OUT + 32 + lane];
    float s1 = v0 * a[lane]      + v1 * a[lane + 32];
    float s2 = v0 * a[64 + lane] + v1 * a[96 + lane];
#pragma unroll
    for (int o = 16; o; o >>= 1) {
        s1 += __shfl_xor_sync(0xffffffffu, s1, o);
        s2 += __shfl_xor_sync(0xffffffffu, s2, o);
    }
    if (lane == 0) { d_e1[row] = s1; d_e2[row] = s2; }
}

// ------------------------- K2: attention per node --------------------------
// grid 4096, block 256
__global__ void k_att(const float* __restrict__ adj) {
    __shared__ int   nbr[64];
    __shared__ float satt[64];
    __shared__ int   wcnt[8];
    __shared__ int   scnt;
    __shared__ float smax, ssum;
    __shared__ float spart[4][64];

    const int i    = blockIdx.x;
    const int tid  = threadIdx.x;
    const int warp = tid >> 5;
    const int lane = tid & 31;

    if (tid == 0) scnt = 0;
    __syncthreads();

    // deterministic neighbor collection (pure block-scan, no atomics)
    for (int base = 0; base < N_NODES; base += 256) {
        const float v = adj[(size_t)i * N_NODES + base + tid];
        const unsigned m = __ballot_sync(0xffffffffu, v > 0.f);
        if (lane == 0) wcnt[warp] = __popc(m);
        __syncthreads();
        int pref = scnt;
        for (int w = 0; w < warp; w++) pref += wcnt[w];
        if (v > 0.f) {
            const int pos = pref + __popc(m & ((1u << lane) - 1u));
            if (pos < 64) nbr[pos] = base + tid;
        }
        __syncthreads();
        if (tid == 0) {
            int t = 0;
            for (int w = 0; w < 8; w++) t += wcnt[w];
            scnt += t;
        }
        __syncthreads();
    }
    const int L = (scnt < 64) ? scnt : 64;

    const float e1i = d_e1[i];
    if (tid < L) {
        float ev = e1i + d_e2[nbr[tid]];
        ev = ev > 0.f ? ev : ALPHA * ev;
        satt[tid] = ev;
    }
    __syncthreads();
    if (tid == 0) {
        float mx = satt[0];
        for (int n = 1; n < L; n++) mx = fmaxf(mx, satt[n]);
        smax = mx;
    }
    __syncthreads();
    if (tid < L) satt[tid] = __expf(satt[tid] - smax);
    __syncthreads();
    if (tid == 0) {
        float s = 0.f;
        for (int n = 0; n < L; n++) s += satt[n];
        ssum = s;
    }
    __syncthreads();
    if (tid < L) satt[tid] = satt[tid] / ssum;
    __syncthreads();

    // stable rank matching jnp.argsort(-att): desc att, ties -> lower j first
    if (tid < L) {
        const float av = satt[tid];
        const int   jv = nbr[tid];
        int rank = 0;
        for (int k = 0; k < L; k++) {
            const float ak = satt[k];
            rank += (ak > av) || (ak == av && nbr[k] < jv);
        }
        d_ord[i * MAX_DEG + rank] = jv;
    }

    // Wh2[i] = sum_n att_n * Wh[nbr_n]  (fixed-order strided partials)
    const int f = tid & 63, s = tid >> 6;
    float part = 0.f;
    for (int n = s; n < L; n += 4)
        part = fmaf(satt[n], d_Wh[nbr[n] * F_OUT + f], part);
    spart[s][f] = part;
    __syncthreads();
    if (s == 0)
        d_Wh2[i * F_OUT + f] = spart[0][f] + spart[1][f] + spart[2][f] + spart[3][f];
}

// ------------------------- K3: counting sort by seq_length desc ------------
__global__ void k_sort_init() {
    const int t = threadIdx.x;
    if (t < 64) d_bins[t] = 0;
    if (t == 0) d_work = 0;
}
__global__ void k_hist(const int* __restrict__ sl) {
    const int i = blockIdx.x * blockDim.x + threadIdx.x;
    if (i < N_NODES) atomicAdd(&d_bins[64 - sl[i]], 1);
}
__global__ void k_scan() {
    if (threadIdx.x == 0) {
        int acc = 0;
        for (int b = 0; b < 64; b++) { d_binoff[b] = acc; acc += d_bins[b]; }
    }
}
__global__ void k_scatter(const int* __restrict__ sl) {
    const int i = blockIdx.x * blockDim.x + threadIdx.x;
    if (i < N_NODES) {
        const int p = atomicAdd(&d_binoff[64 - sl[i]], 1);
        d_sorted[p] = i;
    }
}

// ------------------------- K4: persistent LSTM -----------------------------
#define LSTM_SMEM_FLOATS (2 * 64 * 256 + 256 + 3 * 64 * 16 + NB * GP)
#define LSTM_SMEM_BYTES  (LSTM_SMEM_FLOATS * 4 + 64 * 4)

#define ACC4(A, XC, HC)                              \
    A.x = fmaf(wi.x, XC, fmaf(wh.x, HC, A.x));       \
    A.y = fmaf(wi.y, XC, fmaf(wh.y, HC, A.y));       \
    A.z = fmaf(wi.z, XC, fmaf(wh.z, HC, A.z));       \
    A.w = fmaf(wi.w, XC, fmaf(wh.w, HC, A.w));

__device__ __forceinline__ float sigf(float x) { return 1.f / (1.f + __expf(-x)); }

__global__ __launch_bounds__(256, 1)
void k_lstm(const float* __restrict__ w_ih, const float* __restrict__ w_hh,
            const float* __restrict__ b_ih, const float* __restrict__ b_hh,
            const int* __restrict__ sl, float* __restrict__ out) {
    extern __shared__ float sm[];
    float* s_wih = sm;                      // [64][256]  k-major (transposed)
    float* s_whh = s_wih + 64 * 256;        // [64][256]
    float* s_b   = s_whh + 64 * 256;        // [256]
    float* x_sm  = s_b + 256;               // [64][16]
    float* h_sm  = x_sm + 64 * 16;          // [64][16]
    float* c_sm  = h_sm + 64 * 16;          // [64][16]
    float* g_sm  = c_sm + 64 * 16;          // [16][GP]
    int*   s_node = (int*)(g_sm + NB * GP); // [16]
    int*   s_L    = s_node + NB;            // [16]
    int*   s_meta = s_L + NB;               // [0]=chunk [1]=maxL

    const int tid = threadIdx.x;

    // load transposed weights + fused bias
    for (int idx = tid; idx < 256 * 64; idx += 256) {
        const int g = idx >> 6, k = idx & 63;
        s_wih[k * 256 + g] = w_ih[idx];
        s_whh[k * 256 + g] = w_hh[idx];
    }
    s_b[tid] = b_ih[tid] + b_hh[tid];

    // FIX (R4): barrier before cross-warp read of s_b. Previously bq0 was
    // loaded without a sync — thread tid reads s_b[4*(tid&63)..] written by a
    // DIFFERENT warp, racing with uninitialized SMEM -> garbage gate bias
    // baked into a register for the whole kernel (rel_err 1.63).
    __syncthreads();

    const int q = tid & 63;       // gate quad index
    const int s = tid >> 6;       // node subgroup (4 nodes each)
    const float4* wih4 = (const float4*)s_wih;
    const float4* whh4 = (const float4*)s_whh;
    const float4* x4   = (const float4*)x_sm;
    const float4* h4   = (const float4*)h_sm;
    const float4  bq0  = ((const float4*)s_b)[q];

    while (true) {
        __syncthreads();
        if (tid == 0) s_meta[0] = atomicAdd(&d_work, 1);
        __syncthreads();
        const int chunk = s_meta[0];
        if (chunk >= NCHUNK) break;

        if (tid < NB) {
            const int node = d_sorted[chunk * NB + tid];
            s_node[tid] = node;
            s_L[tid]    = sl[node];
        }
        for (int idx = tid; idx < 64 * 16; idx += 256) {
            h_sm[idx] = 0.f;
            c_sm[idx] = 0.f;
        }
        __syncthreads();
        if (tid == 0) {
            int mx = 0;
            for (int m = 0; m < NB; m++) mx = max(mx, s_L[m]);
            s_meta[1] = mx;
        }
        __syncthreads();
        const int maxL = s_meta[1];

        for (int t = 0; t < maxL; t++) {
            // gather x = Wh2[ord[node][clip(L-1-t,0)]]
            {
                const int m  = tid >> 4, k4 = tid & 15;
                const int L  = s_L[m];
                int idx = L - 1 - t;
                if (idx < 0) idx = 0;
                const int row = d_ord[s_node[m] * MAX_DEG + idx];
                const float4 v = *(const float4*)(&d_Wh2[row * F_OUT + k4 * 4]);
                x_sm[(k4 * 4 + 0) * 16 + m] = v.x;
                x_sm[(k4 * 4 + 1) * 16 + m] = v.y;
                x_sm[(k4 * 4 + 2) * 16 + m] = v.z;
                x_sm[(k4 * 4 + 3) * 16 + m] = v.w;
            }
            __syncthreads();

            float4 acc0 = bq0, acc1 = bq0, acc2 = bq0, acc3 = bq0;
#pragma unroll 8
            for (int k = 0; k < 64; k++) {
                const float4 wi = wih4[k * 64 + q];
                const float4 wh = whh4[k * 64 + q];
                const float4 xv = x4[k * 4 + s];
                const float4 hv = h4[k * 4 + s];
                ACC4(acc0, xv.x, hv.x)
                ACC4(acc1, xv.y, hv.y)
                ACC4(acc2, xv.z, hv.z)
                ACC4(acc3, xv.w, hv.w)
            }
            *((float4*)(g_sm + (4 * s + 0) * GP) + q) = acc0;
            *((float4*)(g_sm + (4 * s + 1) * GP) + q) = acc1;
            *((float4*)(g_sm + (4 * s + 2) * GP) + q) = acc2;
            *((float4*)(g_sm + (4 * s + 3) * GP) + q) = acc3;
            __syncthreads();

            // gate nonlinearity + state update (only active nodes)
#pragma unroll
            for (int rep = 0; rep < 4; rep++) {
                const int idx = tid + rep * 256;
                const int m = idx & 15, u = idx >> 4;
                if (t < s_L[m]) {
                    const float gi = g_sm[m * GP + u];
                    const float gf = g_sm[m * GP + 64 + u];
                    const float gg = g_sm[m * GP + 128 + u];
                    const float go = g_sm[m * GP + 192 + u];
                    const float c  = c_sm[u * 16 + m];
                    const float cn = sigf(gf) * c + sigf(gi) * tanhf(gg);
                    const float hn = sigf(go) * tanhf(cn);
                    c_sm[u * 16 + m] = cn;
                    h_sm[u * 16 + m] = hn;
                }
            }
            __syncthreads();
        }

        // write hn
#pragma unroll
        for (int rep = 0; rep < 4; rep++) {
            const int idx = tid + rep * 256;
            const int m = idx & 15, u = idx >> 4;
            out[s_node[m] * HDIM + u] = h_sm[u * 16 + m];
        }
    }
}

// ------------------------- launch ------------------------------------------
extern "C" void kernel_launch(void* const* d_in, const int* in_sizes, int n_in,
                              void* d_out, int out_size) {
    const float* h   = (const float*)d_in[0];
    const float* adj = (const float*)d_in[1];
    const int*   sl  = (const int*)  d_in[2];
    const float* W   = (const float*)d_in[3];
    const float* a   = (const float*)d_in[4];
    const float* wih = (const float*)d_in[5];
    const float* whh = (const float*)d_in[6];
    const float* bih = (const float*)d_in[7];
    const float* bhh = (const float*)d_in[8];
    float* out = (float*)d_out;

    cudaFuncSetAttribute(k_wh,   cudaFuncAttributeMaxDynamicSharedMemorySize, 96 * 1024);
    cudaFuncSetAttribute(k_lstm, cudaFuncAttributeMaxDynamicSharedMemorySize, LSTM_SMEM_BYTES);

    int sms = 148;
    cudaDeviceGetAttribute(&sms, cudaDevAttrMultiProcessorCount, 0);

    k_wh      <<<128,  256, 96 * 1024>>>(h, W);
    k_e       <<<512,  256>>>(a);
    k_sort_init<<<1,    64>>>();
    k_hist    <<<16,   256>>>(sl);
    k_att     <<<4096, 256>>>(adj);
    k_scan    <<<1,     32>>>();
    k_scatter <<<16,   256>>>(sl);
    k_lstm    <<<sms,  256, LSTM_SMEM_BYTES>>>(wih, whh, bih, bhh, sl, out);
}